// round 15
// baseline (speedup 1.0000x reference)
#include <cuda_runtime.h>
#include <cuda_fp16.h>
#include <stdint.h>
#include <math.h>

#define NN 100000
#define NE 1600000
#define FIN 128
#define FE 16
#define HH 64
#define TT 32
#define SCAN_B 1024
#define NBLK ((NN + SCAN_B - 1) / SCAN_B)   // 98

// ---------------- scratch (device globals; no runtime alloc) ----------------
__device__ __align__(16) __half2 g_h16[NN * 32];   // h in fp16, 64 halves/node
__device__ __align__(16) __half  g_feat16[NN * HH];// layer-1 output (relu'd, fp16)
__device__ float g_hs[NN];
__device__ float g_hd[NN];
__device__ int   g_degi[NN];
__device__ int   g_row[NN + 1];
__device__ int   g_cursor[NN];
__device__ volatile int g_bpub[NBLK];
__device__ __align__(16) int4 g_ecsr[NE];          // {src, cet0, cet1, pad}
__device__ float g_weae[2][FE];

__global__ void k_init(const float* We1, const float* ae1,
                       const float* We2, const float* ae2) {
    int idx = blockIdx.x * blockDim.x + threadIdx.x;
    if (idx < NN) g_degi[idx] = 0;
    if (idx < NBLK) g_bpub[idx] = 0;
    if (idx == 0) g_row[NN] = NE;
    if (blockIdx.x == 0) {
        int t = threadIdx.x;
        if (t < FE) {
            float s = 0.f;
            for (int h = 0; h < HH; h++) s += We1[t * HH + h] * ae1[h];
            g_weae[0][t] = s;
        } else if (t < 2 * FE) {
            int f = t - FE;
            float s = 0.f;
            for (int h = 0; h < HH; h++) s += We2[f * HH + h] * ae2[h];
            g_weae[1][f] = s;
        }
    }
}

__global__ void k_deg(const int* __restrict__ dst) {
    int e = blockIdx.x * blockDim.x + threadIdx.x;
    if (e < NE) atomicAdd(&g_degi[dst[e]], 1);
}

// single-kernel decoupled-lookback scan (98 blocks, all co-resident)
__global__ void k_scan_lb() {
    __shared__ int wsum[32];
    __shared__ int svals[NBLK];
    __shared__ int prevsum;
    int tid = threadIdx.x, lane = tid & 31, wid = tid >> 5;
    int b = blockIdx.x;
    int idx = b * SCAN_B + tid;
    int v = (idx < NN) ? g_degi[idx] : 0;
    int x = v;
#pragma unroll
    for (int o = 1; o < 32; o <<= 1) { int y = __shfl_up_sync(~0u, x, o); if (lane >= o) x += y; }
    if (lane == 31) wsum[wid] = x;
    __syncthreads();
    if (wid == 0) {
        int s = wsum[lane];
#pragma unroll
        for (int o = 1; o < 32; o <<= 1) { int y = __shfl_up_sync(~0u, s, o); if (lane >= o) s += y; }
        wsum[lane] = s;
    }
    __syncthreads();
    int off = wid ? wsum[wid - 1] : 0;
    if (tid == SCAN_B - 1) atomicExch((int*)&g_bpub[b], off + x + 1);
    if (tid < b) {
        int vv;
        do { vv = g_bpub[tid]; } while (vv == 0);
        svals[tid] = vv - 1;
    }
    __syncthreads();
    if (tid == 0) {
        int s = 0;
        for (int i = 0; i < b; i++) s += svals[i];
        prevsum = s;
    }
    __syncthreads();
    if (idx < NN) {
        int r = x - v + off + prevsum;
        g_row[idx] = r;
        g_cursor[idx] = r;
    }
}

__global__ void k_edge_pre(const float* __restrict__ ea, const int* __restrict__ src,
                           const int* __restrict__ dst) {
    int e = blockIdx.x * blockDim.x + threadIdx.x;
    if (e >= NE) return;
    int d = dst[e];
    const float4* v = (const float4*)(ea + (size_t)e * FE);
    float4 a0 = v[0], a1 = v[1], a2 = v[2], a3 = v[3];
    float av[16] = {a0.x, a0.y, a0.z, a0.w, a1.x, a1.y, a1.z, a1.w,
                    a2.x, a2.y, a2.z, a2.w, a3.x, a3.y, a3.z, a3.w};
    float s0 = 0.f, s1 = 0.f;
#pragma unroll
    for (int f = 0; f < FE; f++) {
        s0 += av[f] * g_weae[0][f];
        s1 += av[f] * g_weae[1][f];
    }
    int pos = atomicAdd(&g_cursor[d], 1);
    int4 ent;
    ent.x = src[e];
    ent.y = __float_as_int(s0);
    ent.z = __float_as_int(s1);
    ent.w = 0;
    g_ecsr[pos] = ent;
}

// ---------------- tensor-core GEMM: h = x @ W (fp16 mma, fp32 accum) --------
// 64x64 tile, 8 warps, warp = 16x32 via mma.m16n8k16; fragments via ldmatrix.
template <int DIN, bool FP16IN>
__global__ __launch_bounds__(256) void k_gemm_mma(const float* __restrict__ xf,
                                                  const __half* __restrict__ xh,
                                                  const float* __restrict__ W,
                                                  const float* __restrict__ a_s,
                                                  const float* __restrict__ a_d) {
    constexpr int AS = DIN + 8;                       // padded half stride
    constexpr int STAGE_BYTES = 2 * 64 * AS * 2;
    constexpr int HT_BYTES = 64 * 66 * 4;
    constexpr int SBYTES = STAGE_BYTES > HT_BYTES ? STAGE_BYTES : HT_BYTES;
    __shared__ __align__(16) char smem[SBYTES];
    __half* xs = (__half*)smem;                       // [64][AS]
    __half* Wt = (__half*)(smem + 64 * AS * 2);       // [64][AS]  (n-major)
    float* ht = (float*)smem;                         // [64][66]  (reused)

    int tid = threadIdx.x;
    int lane = tid & 31;
    int wid = tid >> 5;
    int row0 = blockIdx.x * 64;

    // stage A (x rows -> fp16)
    if (FP16IN) {
        for (int i = tid; i < 64 * DIN / 2; i += 256) {
            int row = i / (DIN / 2);
            int k = 2 * (i % (DIN / 2));
            int rr = row0 + row;
            __half2 v = (rr < NN) ? *(const __half2*)(xh + (size_t)rr * DIN + k)
                                  : __floats2half2_rn(0.f, 0.f);
            *(__half2*)&xs[row * AS + k] = v;
        }
    } else {
        for (int i = tid; i < 64 * DIN / 2; i += 256) {
            int row = i / (DIN / 2);
            int k = 2 * (i % (DIN / 2));
            int rr = row0 + row;
            float2 v = (rr < NN) ? *(const float2*)(xf + (size_t)rr * DIN + k)
                                 : make_float2(0.f, 0.f);
            *(__half2*)&xs[row * AS + k] = __floats2half2_rn(v.x, v.y);
        }
    }
    // stage B transposed: Wt[n][k] = W[k][n]
    for (int i = tid; i < 64 * DIN / 2; i += 256) {
        int n = i & 63;
        int kk = i >> 6;
        float w0 = W[(2 * kk) * 64 + n];
        float w1 = W[(2 * kk + 1) * 64 + n];
        *(__half2*)&Wt[n * AS + 2 * kk] = __floats2half2_rn(w0, w1);
    }
    __syncthreads();

    int wm = (wid & 3) * 16;
    int wn = (wid >> 2) * 32;
    float c[4][4] = {};

    // ldmatrix base addresses (32-bit shared addresses)
    // A: matrices {rows wm+0..7,k0}, {wm+8..15,k0}, {wm+0..7,k+8}, {wm+8..15,k+8}
    unsigned int abase = (unsigned int)__cvta_generic_to_shared(
        &xs[(wm + (lane & 15)) * AS + ((lane >> 4) << 3)]);
    // B: n row = wn + lane; low-k matrices for nt groups 0..3
    unsigned int bbase = (unsigned int)__cvta_generic_to_shared(&Wt[(wn + lane) * AS]);

#pragma unroll
    for (int kc = 0; kc < DIN; kc += 16) {
        unsigned int a0, a1, a2, a3;
        asm volatile("ldmatrix.sync.aligned.m8n8.x4.shared.b16 {%0,%1,%2,%3}, [%4];"
                     : "=r"(a0), "=r"(a1), "=r"(a2), "=r"(a3)
                     : "r"(abase + kc * 2));
        unsigned int bl0, bl1, bl2, bl3;
        asm volatile("ldmatrix.sync.aligned.m8n8.x4.shared.b16 {%0,%1,%2,%3}, [%4];"
                     : "=r"(bl0), "=r"(bl1), "=r"(bl2), "=r"(bl3)
                     : "r"(bbase + kc * 2));
        unsigned int bh0, bh1, bh2, bh3;
        asm volatile("ldmatrix.sync.aligned.m8n8.x4.shared.b16 {%0,%1,%2,%3}, [%4];"
                     : "=r"(bh0), "=r"(bh1), "=r"(bh2), "=r"(bh3)
                     : "r"(bbase + kc * 2 + 16));
        asm volatile("mma.sync.aligned.m16n8k16.row.col.f32.f16.f16.f32 "
                     "{%0,%1,%2,%3}, {%4,%5,%6,%7}, {%8,%9}, {%0,%1,%2,%3};"
                     : "+f"(c[0][0]), "+f"(c[0][1]), "+f"(c[0][2]), "+f"(c[0][3])
                     : "r"(a0), "r"(a1), "r"(a2), "r"(a3), "r"(bl0), "r"(bh0));
        asm volatile("mma.sync.aligned.m16n8k16.row.col.f32.f16.f16.f32 "
                     "{%0,%1,%2,%3}, {%4,%5,%6,%7}, {%8,%9}, {%0,%1,%2,%3};"
                     : "+f"(c[1][0]), "+f"(c[1][1]), "+f"(c[1][2]), "+f"(c[1][3])
                     : "r"(a0), "r"(a1), "r"(a2), "r"(a3), "r"(bl1), "r"(bh1));
        asm volatile("mma.sync.aligned.m16n8k16.row.col.f32.f16.f16.f32 "
                     "{%0,%1,%2,%3}, {%4,%5,%6,%7}, {%8,%9}, {%0,%1,%2,%3};"
                     : "+f"(c[2][0]), "+f"(c[2][1]), "+f"(c[2][2]), "+f"(c[2][3])
                     : "r"(a0), "r"(a1), "r"(a2), "r"(a3), "r"(bl2), "r"(bh2));
        asm volatile("mma.sync.aligned.m16n8k16.row.col.f32.f16.f16.f32 "
                     "{%0,%1,%2,%3}, {%4,%5,%6,%7}, {%8,%9}, {%0,%1,%2,%3};"
                     : "+f"(c[3][0]), "+f"(c[3][1]), "+f"(c[3][2]), "+f"(c[3][3])
                     : "r"(a0), "r"(a1), "r"(a2), "r"(a3), "r"(bl3), "r"(bh3));
    }
    __syncthreads();   // staging reads done; smem can be reused

    // store C frags to ht[64][66]
#pragma unroll
    for (int nt = 0; nt < 4; nt++) {
        int col = wn + nt * 8 + 2 * (lane & 3);
        int rr = wm + (lane >> 2);
        *(float2*)&ht[rr * 66 + col] = make_float2(c[nt][0], c[nt][1]);
        *(float2*)&ht[(rr + 8) * 66 + col] = make_float2(c[nt][2], c[nt][3]);
    }
    __syncthreads();

    // epilogue: warp w handles rows 8w..8w+7
    float as0 = a_s[lane], as1 = a_s[lane + 32];
    float ad0 = a_d[lane], ad1 = a_d[lane + 32];
#pragma unroll
    for (int rr = 0; rr < 8; rr++) {
        int r = wid * 8 + rr;
        int row = row0 + r;
        float h0 = ht[r * 66 + lane];
        float h1 = ht[r * 66 + 32 + lane];
        float ps = h0 * as0 + h1 * as1;
        float pd = h0 * ad0 + h1 * ad1;
#pragma unroll
        for (int o = 16; o; o >>= 1) {
            ps += __shfl_xor_sync(~0u, ps, o);
            pd += __shfl_xor_sync(~0u, pd, o);
        }
        if (row < NN) {
            if (lane == 0) { g_hs[row] = ps; g_hd[row] = pd; }
            float2 fr = *(const float2*)&ht[r * 66 + 2 * lane];
            g_h16[(size_t)row * 32 + lane] = __floats2half2_rn(fr.x, fr.y);
        }
    }
}

// One warp per dst node (R8-verified config). feat output fp16.
template <int L, bool FUSE>
__global__ __launch_bounds__(256) void k_aggregate(const float* __restrict__ b,
                                                   const float* __restrict__ Wc1,
                                                   const float* __restrict__ bc1,
                                                   const float* __restrict__ Wc2,
                                                   const float* __restrict__ bc2,
                                                   float* __restrict__ out) {
    int node = blockIdx.x * 8 + (threadIdx.x >> 5);
    int lane = threadIdx.x & 31;
    if (node >= NN) return;
    int beg = g_row[node], end = g_row[node + 1];
    float hd_d = g_hd[node];
    int q = lane >> 3;
    int sub = lane & 7;
    const __half* hbase = (const __half*)g_h16;
    float acc[8] = {};
    float z = 0.f, cs = 0.f;

    for (int base = beg; base < end; base += 32) {
        int i = base + lane;
        bool valid = i < end;
        int4 ent = valid ? g_ecsr[i] : make_int4(0, 0, 0, 0);
        int s = ent.x;
        float c = __int_as_float((L == 0) ? ent.y : ent.z);
        float p = 0.f;
        if (valid) {
            float a = g_hs[s] + hd_d + c;
            a = (a > 0.f) ? a : 0.2f * a;
            p = __expf(a);
            z += p;
            cs += c;
        }
        int cnt = min(32, end - base);
        for (int j = 0; j < cnt; j += 4) {
            int idx = j + q;
            bool vq = idx < cnt;
            int sel = vq ? idx : 0;
            int sj = __shfl_sync(~0u, s, sel);
            float pj = __shfl_sync(~0u, p, sel);
            if (!vq) pj = 0.f;
            uint4 raw = *(const uint4*)(hbase + ((size_t)sj << 6) + (sub << 3));
            float2 f0 = __half22float2(*(const __half2*)&raw.x);
            float2 f1 = __half22float2(*(const __half2*)&raw.y);
            float2 f2 = __half22float2(*(const __half2*)&raw.z);
            float2 f3 = __half22float2(*(const __half2*)&raw.w);
            acc[0] = fmaf(pj, f0.x, acc[0]);
            acc[1] = fmaf(pj, f0.y, acc[1]);
            acc[2] = fmaf(pj, f1.x, acc[2]);
            acc[3] = fmaf(pj, f1.y, acc[3]);
            acc[4] = fmaf(pj, f2.x, acc[4]);
            acc[5] = fmaf(pj, f2.y, acc[5]);
            acc[6] = fmaf(pj, f3.x, acc[6]);
            acc[7] = fmaf(pj, f3.y, acc[7]);
        }
    }
#pragma unroll
    for (int o = 16; o; o >>= 1) {
        z += __shfl_xor_sync(0xffffffffu, z, o);
        cs += __shfl_xor_sync(0xffffffffu, cs, o);
    }
#pragma unroll
    for (int t = 0; t < 8; t++) {
        acc[t] += __shfl_xor_sync(~0u, acc[t], 8);
        acc[t] += __shfl_xor_sync(~0u, acc[t], 16);
    }
    int deg = end - beg;
    float eloop = cs / fmaxf((float)deg, 1.f);
    float al = g_hs[node] + hd_d + eloop;
    al = (al > 0.f) ? al : 0.2f * al;
    float pl = __expf(al);
    z += pl;
    {
        uint4 raw = *(const uint4*)(hbase + ((size_t)node << 6) + (sub << 3));
        float2 f0 = __half22float2(*(const __half2*)&raw.x);
        float2 f1 = __half22float2(*(const __half2*)&raw.y);
        float2 f2 = __half22float2(*(const __half2*)&raw.z);
        float2 f3 = __half22float2(*(const __half2*)&raw.w);
        acc[0] = fmaf(pl, f0.x, acc[0]);
        acc[1] = fmaf(pl, f0.y, acc[1]);
        acc[2] = fmaf(pl, f1.x, acc[2]);
        acc[3] = fmaf(pl, f1.y, acc[3]);
        acc[4] = fmaf(pl, f2.x, acc[4]);
        acc[5] = fmaf(pl, f2.y, acc[5]);
        acc[6] = fmaf(pl, f3.x, acc[6]);
        acc[7] = fmaf(pl, f3.y, acc[7]);
    }
    float inv = 1.f / z;
    float fv[8];
#pragma unroll
    for (int t = 0; t < 8; t++)
        fv[t] = fmaxf(fmaf(acc[t], inv, b[8 * sub + t]), 0.f);

    if (!FUSE) {
        if (lane < 8) {
            __half2 h01 = __floats2half2_rn(fv[0], fv[1]);
            __half2 h23 = __floats2half2_rn(fv[2], fv[3]);
            __half2 h45 = __floats2half2_rn(fv[4], fv[5]);
            __half2 h67 = __floats2half2_rn(fv[6], fv[7]);
            uint4 pk;
            pk.x = *(unsigned int*)&h01;
            pk.y = *(unsigned int*)&h23;
            pk.z = *(unsigned int*)&h45;
            pk.w = *(unsigned int*)&h67;
            *(uint4*)(g_feat16 + (size_t)node * HH + 8 * sub) = pk;
        }
    } else {
        float accm = bc1[lane];
#pragma unroll
        for (int k = 0; k < 64; k++)
            accm = fmaf(__shfl_sync(~0u, fv[k & 7], k >> 3), Wc1[k * 32 + lane], accm);
        float hid = fmaxf(accm, 0.f);
        float lg = bc2[lane];
#pragma unroll
        for (int jj = 0; jj < 32; jj++)
            lg = fmaf(__shfl_sync(~0u, hid, jj), Wc2[jj * TT + lane], lg);
        out[(size_t)node * TT + lane] = lg;
    }
}

extern "C" void kernel_launch(void* const* d_in, const int* in_sizes, int n_in,
                              void* d_out, int out_size) {
    const float* x   = (const float*)d_in[0];
    const int*   ei  = (const int*)d_in[1];
    const float* ea  = (const float*)d_in[2];
    const float* W1  = (const float*)d_in[3];
    const float* as1 = (const float*)d_in[4];
    const float* ad1 = (const float*)d_in[5];
    const float* We1 = (const float*)d_in[6];
    const float* ae1 = (const float*)d_in[7];
    const float* b1  = (const float*)d_in[8];
    const float* W2  = (const float*)d_in[9];
    const float* as2 = (const float*)d_in[10];
    const float* ad2 = (const float*)d_in[11];
    const float* We2 = (const float*)d_in[12];
    const float* ae2 = (const float*)d_in[13];
    const float* b2  = (const float*)d_in[14];
    const float* Wc1 = (const float*)d_in[15];
    const float* bc1 = (const float*)d_in[16];
    const float* Wc2 = (const float*)d_in[17];
    const float* bc2 = (const float*)d_in[18];
    float* out = (float*)d_out;

    const int* src = ei;
    const int* dst = ei + NE;

    __half* d_feat16;
    cudaGetSymbolAddress((void**)&d_feat16, g_feat16);

    static cudaStream_t s2 = nullptr;
    static cudaEvent_t evFork = nullptr, evJoin = nullptr;
    if (!s2) {
        cudaStreamCreateWithFlags(&s2, cudaStreamNonBlocking);
        cudaEventCreateWithFlags(&evFork, cudaEventDisableTiming);
        cudaEventCreateWithFlags(&evJoin, cudaEventDisableTiming);
    }

    cudaEventRecord(evFork, 0);
    cudaStreamWaitEvent(s2, evFork, 0);

    k_init<<<(NN + 255) / 256, 256>>>(We1, ae1, We2, ae2);   // 1
    k_deg<<<(NE + 255) / 256, 256>>>(dst);                   // 2
    k_scan_lb<<<NBLK, SCAN_B>>>();                           // 3
    k_gemm_mma<FIN, false><<<(NN + 63) / 64, 256, 0, s2>>>(x, nullptr, W1, as1, ad1);  // 4 <- PROFILED
    cudaEventRecord(evJoin, s2);
    k_edge_pre<<<(NE + 255) / 256, 256>>>(ea, src, dst);     // 5

    cudaStreamWaitEvent(0, evJoin, 0);

    // ---- layer 1 ----
    k_aggregate<0, false><<<(NN + 7) / 8, 256>>>(b1, nullptr, nullptr, nullptr, nullptr, nullptr);

    // ---- layer 2 (+ fused classifier) ----
    k_gemm_mma<HH, true><<<(NN + 63) / 64, 256>>>(nullptr, d_feat16, W2, as2, ad2);
    k_aggregate<1, true><<<(NN + 7) / 8, 256>>>(b2, Wc1, bc1, Wc2, bc2, out);
}

// round 16
// speedup vs baseline: 1.0213x; 1.0213x over previous
#include <cuda_runtime.h>
#include <cuda_fp16.h>
#include <stdint.h>
#include <math.h>

#define NN 100000
#define NE 1600000
#define FIN 128
#define FE 16
#define HH 64
#define TT 32
#define SCAN_B 1024
#define NBLK ((NN + SCAN_B - 1) / SCAN_B)   // 98

// ---------------- scratch (device globals; no runtime alloc) ----------------
__device__ __align__(16) __half2 g_h16[NN * 32];   // h in fp16, 64 halves/node
__device__ __align__(16) __half  g_feat16[NN * HH];// layer-1 output (relu'd, fp16)
__device__ float g_hs[NN];
__device__ float g_hd[NN];
__device__ int   g_degi[NN];
__device__ int   g_row[NN + 1];
__device__ int   g_cursor[NN];
__device__ volatile int g_bpub[NBLK];
__device__ __align__(16) int4 g_ecsr[NE];          // {src, cet0, cet1, pad}
__device__ float g_weae[2][FE];

__global__ void k_init(const float* We1, const float* ae1,
                       const float* We2, const float* ae2) {
    int idx = blockIdx.x * blockDim.x + threadIdx.x;
    if (idx < NN) g_degi[idx] = 0;
    if (idx < NBLK) g_bpub[idx] = 0;
    if (idx == 0) g_row[NN] = NE;
    if (blockIdx.x == 0) {
        int t = threadIdx.x;
        if (t < FE) {
            float s = 0.f;
            for (int h = 0; h < HH; h++) s += We1[t * HH + h] * ae1[h];
            g_weae[0][t] = s;
        } else if (t < 2 * FE) {
            int f = t - FE;
            float s = 0.f;
            for (int h = 0; h < HH; h++) s += We2[f * HH + h] * ae2[h];
            g_weae[1][f] = s;
        }
    }
}

__global__ void k_deg(const int* __restrict__ dst) {
    int e = blockIdx.x * blockDim.x + threadIdx.x;
    if (e < NE) atomicAdd(&g_degi[dst[e]], 1);
}

// single-kernel decoupled-lookback scan (98 blocks, all co-resident)
__global__ void k_scan_lb() {
    __shared__ int wsum[32];
    __shared__ int svals[NBLK];
    __shared__ int prevsum;
    int tid = threadIdx.x, lane = tid & 31, wid = tid >> 5;
    int b = blockIdx.x;
    int idx = b * SCAN_B + tid;
    int v = (idx < NN) ? g_degi[idx] : 0;
    int x = v;
#pragma unroll
    for (int o = 1; o < 32; o <<= 1) { int y = __shfl_up_sync(~0u, x, o); if (lane >= o) x += y; }
    if (lane == 31) wsum[wid] = x;
    __syncthreads();
    if (wid == 0) {
        int s = wsum[lane];
#pragma unroll
        for (int o = 1; o < 32; o <<= 1) { int y = __shfl_up_sync(~0u, s, o); if (lane >= o) s += y; }
        wsum[lane] = s;
    }
    __syncthreads();
    int off = wid ? wsum[wid - 1] : 0;
    if (tid == SCAN_B - 1) atomicExch((int*)&g_bpub[b], off + x + 1);
    if (tid < b) {
        int vv;
        do { vv = g_bpub[tid]; } while (vv == 0);
        svals[tid] = vv - 1;
    }
    __syncthreads();
    if (tid == 0) {
        int s = 0;
        for (int i = 0; i < b; i++) s += svals[i];
        prevsum = s;
    }
    __syncthreads();
    if (idx < NN) {
        int r = x - v + off + prevsum;
        g_row[idx] = r;
        g_cursor[idx] = r;
    }
}

__global__ void k_edge_pre(const float* __restrict__ ea, const int* __restrict__ src,
                           const int* __restrict__ dst) {
    int e = blockIdx.x * blockDim.x + threadIdx.x;
    if (e >= NE) return;
    int d = dst[e];
    const float4* v = (const float4*)(ea + (size_t)e * FE);
    float4 a0 = v[0], a1 = v[1], a2 = v[2], a3 = v[3];
    float av[16] = {a0.x, a0.y, a0.z, a0.w, a1.x, a1.y, a1.z, a1.w,
                    a2.x, a2.y, a2.z, a2.w, a3.x, a3.y, a3.z, a3.w};
    float s0 = 0.f, s1 = 0.f;
#pragma unroll
    for (int f = 0; f < FE; f++) {
        s0 += av[f] * g_weae[0][f];
        s1 += av[f] * g_weae[1][f];
    }
    int pos = atomicAdd(&g_cursor[d], 1);
    int4 ent;
    ent.x = src[e];
    ent.y = __float_as_int(s0);
    ent.z = __float_as_int(s1);
    ent.w = 0;
    g_ecsr[pos] = ent;
}

// ---------------- tensor-core GEMM: h = x @ W (fp16 mma, fp32 accum) --------
// 128x64 tile, 8 warps; warp = 16x64 strip (8 mma per k-chunk).
// Fragment-direct epilogue: hs/hd from C frags, g_h16 written from frags.
template <int DIN, bool FP16IN>
__global__ __launch_bounds__(256) void k_gemm_mma(const float* __restrict__ xf,
                                                  const __half* __restrict__ xh,
                                                  const float* __restrict__ W,
                                                  const float* __restrict__ a_s,
                                                  const float* __restrict__ a_d) {
    constexpr int AS = DIN + 8;                       // padded half stride
    extern __shared__ __align__(16) char smem[];
    __half* xs = (__half*)smem;                       // [128][AS]
    __half* Wt = (__half*)(smem + 128 * AS * 2);      // [64][AS]  (n-major)

    int tid = threadIdx.x;
    int lane = tid & 31;
    int wid = tid >> 5;
    int row0 = blockIdx.x * 128;

    // stage A (x rows -> fp16), 128 rows
    if (FP16IN) {
        for (int i = tid; i < 128 * DIN / 2; i += 256) {
            int row = i / (DIN / 2);
            int k = 2 * (i % (DIN / 2));
            int rr = row0 + row;
            __half2 v = (rr < NN) ? *(const __half2*)(xh + (size_t)rr * DIN + k)
                                  : __floats2half2_rn(0.f, 0.f);
            *(__half2*)&xs[row * AS + k] = v;
        }
    } else {
        for (int i = tid; i < 128 * DIN / 2; i += 256) {
            int row = i / (DIN / 2);
            int k = 2 * (i % (DIN / 2));
            int rr = row0 + row;
            float2 v = (rr < NN) ? *(const float2*)(xf + (size_t)rr * DIN + k)
                                 : make_float2(0.f, 0.f);
            *(__half2*)&xs[row * AS + k] = __floats2half2_rn(v.x, v.y);
        }
    }
    // stage B transposed: Wt[n][k] = W[k][n]
    for (int i = tid; i < 64 * DIN / 2; i += 256) {
        int n = i & 63;
        int kk = i >> 6;
        float w0 = W[(2 * kk) * 64 + n];
        float w1 = W[(2 * kk + 1) * 64 + n];
        *(__half2*)&Wt[n * AS + 2 * kk] = __floats2half2_rn(w0, w1);
    }
    __syncthreads();

    int wm = wid * 16;
    float c[8][4] = {};

    unsigned int abase = (unsigned int)__cvta_generic_to_shared(
        &xs[(wm + (lane & 15)) * AS + ((lane >> 4) << 3)]);
    unsigned int bbase0 = (unsigned int)__cvta_generic_to_shared(&Wt[lane * AS]);
    unsigned int bbase1 = (unsigned int)__cvta_generic_to_shared(&Wt[(32 + lane) * AS]);

#pragma unroll
    for (int kc = 0; kc < DIN; kc += 16) {
        unsigned int a0, a1, a2, a3;
        asm volatile("ldmatrix.sync.aligned.m8n8.x4.shared.b16 {%0,%1,%2,%3}, [%4];"
                     : "=r"(a0), "=r"(a1), "=r"(a2), "=r"(a3)
                     : "r"(abase + kc * 2));
        unsigned int l0, l1, l2, l3, h0, h1, h2, h3;
        asm volatile("ldmatrix.sync.aligned.m8n8.x4.shared.b16 {%0,%1,%2,%3}, [%4];"
                     : "=r"(l0), "=r"(l1), "=r"(l2), "=r"(l3)
                     : "r"(bbase0 + kc * 2));
        asm volatile("ldmatrix.sync.aligned.m8n8.x4.shared.b16 {%0,%1,%2,%3}, [%4];"
                     : "=r"(h0), "=r"(h1), "=r"(h2), "=r"(h3)
                     : "r"(bbase0 + kc * 2 + 16));
        unsigned int l4, l5, l6, l7, h4, h5, h6, h7;
        asm volatile("ldmatrix.sync.aligned.m8n8.x4.shared.b16 {%0,%1,%2,%3}, [%4];"
                     : "=r"(l4), "=r"(l5), "=r"(l6), "=r"(l7)
                     : "r"(bbase1 + kc * 2));
        asm volatile("ldmatrix.sync.aligned.m8n8.x4.shared.b16 {%0,%1,%2,%3}, [%4];"
                     : "=r"(h4), "=r"(h5), "=r"(h6), "=r"(h7)
                     : "r"(bbase1 + kc * 2 + 16));
#define MMA_STEP(G, BL, BH) \
        asm volatile("mma.sync.aligned.m16n8k16.row.col.f32.f16.f16.f32 " \
                     "{%0,%1,%2,%3}, {%4,%5,%6,%7}, {%8,%9}, {%0,%1,%2,%3};" \
                     : "+f"(c[G][0]), "+f"(c[G][1]), "+f"(c[G][2]), "+f"(c[G][3]) \
                     : "r"(a0), "r"(a1), "r"(a2), "r"(a3), "r"(BL), "r"(BH))
        MMA_STEP(0, l0, h0);
        MMA_STEP(1, l1, h1);
        MMA_STEP(2, l2, h2);
        MMA_STEP(3, l3, h3);
        MMA_STEP(4, l4, h4);
        MMA_STEP(5, l5, h5);
        MMA_STEP(6, l6, h6);
        MMA_STEP(7, l7, h7);
#undef MMA_STEP
    }

    // fragment-direct epilogue
    float hs1 = 0.f, hd1 = 0.f, hs2 = 0.f, hd2 = 0.f;
#pragma unroll
    for (int nt = 0; nt < 8; nt++) {
        int cn = nt * 8 + 2 * (lane & 3);
        float as0 = a_s[cn], as1 = a_s[cn + 1];
        float ad0 = a_d[cn], ad1 = a_d[cn + 1];
        hs1 += c[nt][0] * as0 + c[nt][1] * as1;
        hd1 += c[nt][0] * ad0 + c[nt][1] * ad1;
        hs2 += c[nt][2] * as0 + c[nt][3] * as1;
        hd2 += c[nt][2] * ad0 + c[nt][3] * ad1;
    }
#pragma unroll
    for (int o = 1; o < 4; o <<= 1) {
        hs1 += __shfl_xor_sync(~0u, hs1, o);
        hd1 += __shfl_xor_sync(~0u, hd1, o);
        hs2 += __shfl_xor_sync(~0u, hs2, o);
        hd2 += __shfl_xor_sync(~0u, hd2, o);
    }
    int r1 = row0 + wm + (lane >> 2);
    int r2 = r1 + 8;
    bool v1 = r1 < NN, v2 = r2 < NN;
#pragma unroll
    for (int nt = 0; nt < 8; nt++) {
        int col = nt * 4 + (lane & 3);
        if (v1) g_h16[(size_t)r1 * 32 + col] = __floats2half2_rn(c[nt][0], c[nt][1]);
        if (v2) g_h16[(size_t)r2 * 32 + col] = __floats2half2_rn(c[nt][2], c[nt][3]);
    }
    if ((lane & 3) == 0) {
        if (v1) { g_hs[r1] = hs1; g_hd[r1] = hd1; }
        if (v2) { g_hs[r2] = hs2; g_hd[r2] = hd2; }
    }
}

// One warp per dst node (R8-verified config). feat output fp16.
template <int L, bool FUSE>
__global__ __launch_bounds__(256) void k_aggregate(const float* __restrict__ b,
                                                   const float* __restrict__ Wc1,
                                                   const float* __restrict__ bc1,
                                                   const float* __restrict__ Wc2,
                                                   const float* __restrict__ bc2,
                                                   float* __restrict__ out) {
    int node = blockIdx.x * 8 + (threadIdx.x >> 5);
    int lane = threadIdx.x & 31;
    if (node >= NN) return;
    int beg = g_row[node], end = g_row[node + 1];
    float hd_d = g_hd[node];
    int q = lane >> 3;
    int sub = lane & 7;
    const __half* hbase = (const __half*)g_h16;
    float acc[8] = {};
    float z = 0.f, cs = 0.f;

    for (int base = beg; base < end; base += 32) {
        int i = base + lane;
        bool valid = i < end;
        int4 ent = valid ? g_ecsr[i] : make_int4(0, 0, 0, 0);
        int s = ent.x;
        float c = __int_as_float((L == 0) ? ent.y : ent.z);
        float p = 0.f;
        if (valid) {
            float a = g_hs[s] + hd_d + c;
            a = (a > 0.f) ? a : 0.2f * a;
            p = __expf(a);
            z += p;
            cs += c;
        }
        int cnt = min(32, end - base);
        for (int j = 0; j < cnt; j += 4) {
            int idx = j + q;
            bool vq = idx < cnt;
            int sel = vq ? idx : 0;
            int sj = __shfl_sync(~0u, s, sel);
            float pj = __shfl_sync(~0u, p, sel);
            if (!vq) pj = 0.f;
            uint4 raw = *(const uint4*)(hbase + ((size_t)sj << 6) + (sub << 3));
            float2 f0 = __half22float2(*(const __half2*)&raw.x);
            float2 f1 = __half22float2(*(const __half2*)&raw.y);
            float2 f2 = __half22float2(*(const __half2*)&raw.z);
            float2 f3 = __half22float2(*(const __half2*)&raw.w);
            acc[0] = fmaf(pj, f0.x, acc[0]);
            acc[1] = fmaf(pj, f0.y, acc[1]);
            acc[2] = fmaf(pj, f1.x, acc[2]);
            acc[3] = fmaf(pj, f1.y, acc[3]);
            acc[4] = fmaf(pj, f2.x, acc[4]);
            acc[5] = fmaf(pj, f2.y, acc[5]);
            acc[6] = fmaf(pj, f3.x, acc[6]);
            acc[7] = fmaf(pj, f3.y, acc[7]);
        }
    }
#pragma unroll
    for (int o = 16; o; o >>= 1) {
        z += __shfl_xor_sync(0xffffffffu, z, o);
        cs += __shfl_xor_sync(0xffffffffu, cs, o);
    }
#pragma unroll
    for (int t = 0; t < 8; t++) {
        acc[t] += __shfl_xor_sync(~0u, acc[t], 8);
        acc[t] += __shfl_xor_sync(~0u, acc[t], 16);
    }
    int deg = end - beg;
    float eloop = cs / fmaxf((float)deg, 1.f);
    float al = g_hs[node] + hd_d + eloop;
    al = (al > 0.f) ? al : 0.2f * al;
    float pl = __expf(al);
    z += pl;
    {
        uint4 raw = *(const uint4*)(hbase + ((size_t)node << 6) + (sub << 3));
        float2 f0 = __half22float2(*(const __half2*)&raw.x);
        float2 f1 = __half22float2(*(const __half2*)&raw.y);
        float2 f2 = __half22float2(*(const __half2*)&raw.z);
        float2 f3 = __half22float2(*(const __half2*)&raw.w);
        acc[0] = fmaf(pl, f0.x, acc[0]);
        acc[1] = fmaf(pl, f0.y, acc[1]);
        acc[2] = fmaf(pl, f1.x, acc[2]);
        acc[3] = fmaf(pl, f1.y, acc[3]);
        acc[4] = fmaf(pl, f2.x, acc[4]);
        acc[5] = fmaf(pl, f2.y, acc[5]);
        acc[6] = fmaf(pl, f3.x, acc[6]);
        acc[7] = fmaf(pl, f3.y, acc[7]);
    }
    float inv = 1.f / z;
    float fv[8];
#pragma unroll
    for (int t = 0; t < 8; t++)
        fv[t] = fmaxf(fmaf(acc[t], inv, b[8 * sub + t]), 0.f);

    if (!FUSE) {
        if (lane < 8) {
            __half2 h01 = __floats2half2_rn(fv[0], fv[1]);
            __half2 h23 = __floats2half2_rn(fv[2], fv[3]);
            __half2 h45 = __floats2half2_rn(fv[4], fv[5]);
            __half2 h67 = __floats2half2_rn(fv[6], fv[7]);
            uint4 pk;
            pk.x = *(unsigned int*)&h01;
            pk.y = *(unsigned int*)&h23;
            pk.z = *(unsigned int*)&h45;
            pk.w = *(unsigned int*)&h67;
            *(uint4*)(g_feat16 + (size_t)node * HH + 8 * sub) = pk;
        }
    } else {
        float accm = bc1[lane];
#pragma unroll
        for (int k = 0; k < 64; k++)
            accm = fmaf(__shfl_sync(~0u, fv[k & 7], k >> 3), Wc1[k * 32 + lane], accm);
        float hid = fmaxf(accm, 0.f);
        float lg = bc2[lane];
#pragma unroll
        for (int jj = 0; jj < 32; jj++)
            lg = fmaf(__shfl_sync(~0u, hid, jj), Wc2[jj * TT + lane], lg);
        out[(size_t)node * TT + lane] = lg;
    }
}

extern "C" void kernel_launch(void* const* d_in, const int* in_sizes, int n_in,
                              void* d_out, int out_size) {
    const float* x   = (const float*)d_in[0];
    const int*   ei  = (const int*)d_in[1];
    const float* ea  = (const float*)d_in[2];
    const float* W1  = (const float*)d_in[3];
    const float* as1 = (const float*)d_in[4];
    const float* ad1 = (const float*)d_in[5];
    const float* We1 = (const float*)d_in[6];
    const float* ae1 = (const float*)d_in[7];
    const float* b1  = (const float*)d_in[8];
    const float* W2  = (const float*)d_in[9];
    const float* as2 = (const float*)d_in[10];
    const float* ad2 = (const float*)d_in[11];
    const float* We2 = (const float*)d_in[12];
    const float* ae2 = (const float*)d_in[13];
    const float* b2  = (const float*)d_in[14];
    const float* Wc1 = (const float*)d_in[15];
    const float* bc1 = (const float*)d_in[16];
    const float* Wc2 = (const float*)d_in[17];
    const float* bc2 = (const float*)d_in[18];
    float* out = (float*)d_out;

    const int* src = ei;
    const int* dst = ei + NE;

    __half* d_feat16;
    cudaGetSymbolAddress((void**)&d_feat16, g_feat16);

    const int SMEM1 = (128 + 64) * (FIN + 8) * 2;   // 52224
    const int SMEM2 = (128 + 64) * (HH + 8) * 2;    // 27648

    static cudaStream_t s2 = nullptr;
    static cudaEvent_t evFork = nullptr, evJoin = nullptr;
    if (!s2) {
        cudaStreamCreateWithFlags(&s2, cudaStreamNonBlocking);
        cudaEventCreateWithFlags(&evFork, cudaEventDisableTiming);
        cudaEventCreateWithFlags(&evJoin, cudaEventDisableTiming);
        cudaFuncSetAttribute(k_gemm_mma<FIN, false>,
                             cudaFuncAttributeMaxDynamicSharedMemorySize, SMEM1);
        cudaFuncSetAttribute(k_gemm_mma<HH, true>,
                             cudaFuncAttributeMaxDynamicSharedMemorySize, SMEM2);
    }

    cudaEventRecord(evFork, 0);
    cudaStreamWaitEvent(s2, evFork, 0);

    k_init<<<(NN + 255) / 256, 256>>>(We1, ae1, We2, ae2);   // 1
    k_deg<<<(NE + 255) / 256, 256>>>(dst);                   // 2
    k_scan_lb<<<NBLK, SCAN_B>>>();                           // 3
    k_gemm_mma<FIN, false><<<(NN + 127) / 128, 256, SMEM1, s2>>>(x, nullptr, W1, as1, ad1);  // 4 <- PROFILED
    cudaEventRecord(evJoin, s2);
    k_edge_pre<<<(NE + 255) / 256, 256>>>(ea, src, dst);     // 5

    cudaStreamWaitEvent(0, evJoin, 0);

    // ---- layer 1 ----
    k_aggregate<0, false><<<(NN + 7) / 8, 256>>>(b1, nullptr, nullptr, nullptr, nullptr, nullptr);

    // ---- layer 2 (+ fused classifier) ----
    k_gemm_mma<HH, true><<<(NN + 127) / 128, 256, SMEM2>>>(nullptr, d_feat16, W2, as2, ad2);
    k_aggregate<1, true><<<(NN + 7) / 8, 256>>>(b2, Wc1, bc1, Wc2, bc2, out);
}